// round 3
// baseline (speedup 1.0000x reference)
#include <cuda_runtime.h>

#define MAXN     102400
#define CAP      96
#define MAXOVF   3400000
#define IN_FEATS 16

// Scratch (device globals — no allocation allowed)
__device__ int    g_cnt[MAXN];          // degree + bin cursor
__device__ int    g_bin[MAXN * CAP];    // per-dst src lists (~39 MB)
__device__ int2   g_ovf[MAXOVF];        // overflow edges (normally empty)
__device__ int    g_ovf_n;
__device__ float  g_norm[MAXN];
__device__ float4 g_Us[MAXN];           // norm-prescaled X0·[M1|M2]
__device__ float2 g_XA[MAXN];           // X0·M0
__device__ float4 g_Vacc[MAXN];         // pass-1 sums
__device__ float2 g_Zs[MAXN];           // norm²-scaled M2-half of pass-1
__device__ float2 g_P1[MAXN];           // finalized P0·M1
__device__ float2 g_Tacc[MAXN];         // pass-2 sums
__device__ float  g_M0[32], g_M1[32], g_M2[32];
__device__ int    g_is64;

// --- detect int32 vs int64 indices ---
__global__ void k_detect(const unsigned* __restrict__ w, int E) {
    __shared__ int s_any;
    if (threadIdx.x == 0) s_any = 0;
    __syncthreads();
    int limit = (E < 4096) ? E : 4096;
    for (int k = threadIdx.x; k < limit; k += blockDim.x)
        if (w[2 * k + 1] != 0u) s_any = 1;
    __syncthreads();
    if (threadIdx.x == 0) g_is64 = (s_any == 0) ? 1 : 0;
}

// --- zero counters + fold weight matrices ---
__global__ void k_init(const float* __restrict__ W,
                       const float* __restrict__ lam, int N) {
    int i = blockIdx.x * blockDim.x + threadIdx.x;
    if (i < N) g_cnt[i] = 0;
    if (i == 0) g_ovf_n = 0;
    if (blockIdx.x == 0 && threadIdx.x < 32) {
        int j = threadIdx.x >> 1, o = threadIdx.x & 1;
        float r = 2.0f / __ldg(lam);
        float A = __ldg(W + o * 48 + j);
        float B = __ldg(W + o * 48 + 16 + j);
        float C = __ldg(W + o * 48 + 32 + j);
        float rm1 = r - 1.0f;
        g_M0[threadIdx.x] = A + rm1 * B + (2.0f * rm1 * rm1 - 1.0f) * C;
        g_M1[threadIdx.x] = -r * B - 4.0f * r * rm1 * C;
        g_M2[threadIdx.x] = 2.0f * r * r * C;
    }
}

// --- THE single atomic pass: bin edges by dst, count degrees ---
__global__ void k_scatter(const void* __restrict__ srcv,
                          const void* __restrict__ dstv, int E) {
    int e = blockIdx.x * blockDim.x + threadIdx.x;
    if (e >= E) return;
    int s, d;
    if (g_is64) {
        s = (int)__ldcs((const long long*)srcv + e);
        d = (int)__ldcs((const long long*)dstv + e);
    } else {
        s = __ldcs((const int*)srcv + e);
        d = __ldcs((const int*)dstv + e);
    }
    int pos = atomicAdd(&g_cnt[d], 1);
    if (pos < CAP) {
        g_bin[d * CAP + pos] = s;
    } else {
        int j = atomicAdd(&g_ovf_n, 1);
        g_ovf[j] = make_int2(s, d);
    }
}

// --- per-node: norm + projections ---
__global__ void k_node(const float* __restrict__ x, int N) {
    int i = blockIdx.x * blockDim.x + threadIdx.x;
    if (i >= N) return;
    float nrm = rsqrtf((float)max(g_cnt[i], 1));
    g_norm[i] = nrm;
    float u0 = 0.f, u1 = 0.f, u2 = 0.f, u3 = 0.f, a0 = 0.f, a1 = 0.f;
    const float4* xr = (const float4*)(x + (size_t)i * IN_FEATS);
#pragma unroll
    for (int q = 0; q < 4; q++) {
        float4 xv = __ldg(xr + q);
        float vals[4] = {xv.x, xv.y, xv.z, xv.w};
#pragma unroll
        for (int t = 0; t < 4; t++) {
            int j = q * 4 + t;
            float xj = vals[t];
            a0 += xj * g_M0[2 * j];  a1 += xj * g_M0[2 * j + 1];
            u0 += xj * g_M1[2 * j];  u1 += xj * g_M1[2 * j + 1];
            u2 += xj * g_M2[2 * j];  u3 += xj * g_M2[2 * j + 1];
        }
    }
    g_Us[i] = make_float4(u0 * nrm, u1 * nrm, u2 * nrm, u3 * nrm);
    g_XA[i] = make_float2(a0, a1);
}

// --- gather pass 1 (atomic-free): 8 lanes per node ---
__global__ void k_gather1(int N) {
    int t = blockIdx.x * blockDim.x + threadIdx.x;
    int node = t >> 3;
    int sl = t & 7;
    bool valid = (node < N);
    int m = valid ? min(g_cnt[node], CAP) : 0;
    float4 acc = make_float4(0.f, 0.f, 0.f, 0.f);
    const int* row = g_bin + (valid ? node : 0) * CAP;
    for (int k = sl; k < m; k += 8) {
        int s = __ldg(row + k);
        float4 u = __ldg(&g_Us[s]);
        acc.x += u.x; acc.y += u.y; acc.z += u.z; acc.w += u.w;
    }
#pragma unroll
    for (int off = 4; off; off >>= 1) {
        acc.x += __shfl_down_sync(0xffffffffu, acc.x, off, 8);
        acc.y += __shfl_down_sync(0xffffffffu, acc.y, off, 8);
        acc.z += __shfl_down_sync(0xffffffffu, acc.z, off, 8);
        acc.w += __shfl_down_sync(0xffffffffu, acc.w, off, 8);
    }
    if (valid && sl == 0) g_Vacc[node] = acc;
}

// --- overflow fallback pass 1 (empty in practice) ---
__global__ void k_ovf1() {
    int n = g_ovf_n;
    for (int i = blockIdx.x * blockDim.x + threadIdx.x; i < n;
         i += gridDim.x * blockDim.x) {
        int2 e = g_ovf[i];
        float4 u = __ldg(&g_Us[e.x]);
        atomicAdd(&g_Vacc[e.y], u);
    }
}

// --- finalize pass 1 ---
__global__ void k_fin1(int N) {
    int i = blockIdx.x * blockDim.x + threadIdx.x;
    if (i >= N) return;
    float nrm = g_norm[i];
    float4 v  = g_Vacc[i];
    g_P1[i] = make_float2(v.x * nrm, v.y * nrm);
    float n2 = nrm * nrm;
    g_Zs[i] = make_float2(v.z * n2, v.w * n2);
}

// --- gather pass 2 (atomic-free) ---
__global__ void k_gather2(int N) {
    int t = blockIdx.x * blockDim.x + threadIdx.x;
    int node = t >> 3;
    int sl = t & 7;
    bool valid = (node < N);
    int m = valid ? min(g_cnt[node], CAP) : 0;
    float2 acc = make_float2(0.f, 0.f);
    const int* row = g_bin + (valid ? node : 0) * CAP;
    for (int k = sl; k < m; k += 8) {
        int s = __ldg(row + k);
        float2 z = __ldg(&g_Zs[s]);
        acc.x += z.x; acc.y += z.y;
    }
#pragma unroll
    for (int off = 4; off; off >>= 1) {
        acc.x += __shfl_down_sync(0xffffffffu, acc.x, off, 8);
        acc.y += __shfl_down_sync(0xffffffffu, acc.y, off, 8);
    }
    if (valid && sl == 0) g_Tacc[node] = acc;
}

// --- overflow fallback pass 2 ---
__global__ void k_ovf2() {
    int n = g_ovf_n;
    for (int i = blockIdx.x * blockDim.x + threadIdx.x; i < n;
         i += gridDim.x * blockDim.x) {
        int2 e = g_ovf[i];
        float2 z = __ldg(&g_Zs[e.x]);
        atomicAdd(&g_Tacc[e.y], z);
    }
}

// --- epilogue ---
__global__ void k_out(float2* __restrict__ out, int N) {
    int i = blockIdx.x * blockDim.x + threadIdx.x;
    if (i >= N) return;
    float nrm = g_norm[i];
    float2 t = g_Tacc[i], p = g_P1[i], a = g_XA[i];
    out[i] = make_float2(fmaxf(a.x + p.x + t.x * nrm, 0.0f),
                         fmaxf(a.y + p.y + t.y * nrm, 0.0f));
}

extern "C" void kernel_launch(void* const* d_in, const int* in_sizes, int n_in,
                              void* d_out, int out_size) {
    const float* in_feat = (const float*)d_in[0];
    const float* W       = (const float*)d_in[1];
    const void*  src     = d_in[2];
    const void*  dst     = d_in[3];
    const float* lam     = (const float*)d_in[4];

    int N = in_sizes[0] / IN_FEATS;
    int E = in_sizes[2];
    const int TB = 256;
    int nb = (N + TB - 1) / TB;
    int eb = (E + TB - 1) / TB;
    int gb = (N * 8 + TB - 1) / TB;   // 8 lanes per node

    k_detect<<<1, 256>>>((const unsigned*)src, E);
    k_init<<<nb, TB>>>(W, lam, N);
    k_scatter<<<eb, TB>>>(src, dst, E);
    k_node<<<nb, TB>>>(in_feat, N);
    k_gather1<<<gb, TB>>>(N);
    k_ovf1<<<512, TB>>>();
    k_fin1<<<nb, TB>>>(N);
    k_gather2<<<gb, TB>>>(N);
    k_ovf2<<<512, TB>>>();
    k_out<<<nb, TB>>>((float2*)d_out, N);
}

// round 4
// speedup vs baseline: 1.0233x; 1.0233x over previous
#include <cuda_runtime.h>

#define MAXN     102400
#define MAXE     3400000
#define IN_FEATS 16
#define UNROLL   4

// Scratch (device globals — no allocation allowed)
__device__ int    g_deg[MAXN];
__device__ float  g_norm[MAXN];
__device__ float4 g_Us[MAXN];    // norm-prescaled X0·[M1|M2]
__device__ float2 g_XA[MAXN];    // X0·M0
__device__ float4 g_Vacc[MAXN];  // pass-1 accumulator
__device__ float2 g_Zs[MAXN];    // norm²-scaled M2-half of pass-1 result
__device__ float2 g_P1[MAXN];    // finalized P0·M1
__device__ float2 g_Tacc[MAXN];  // pass-2 accumulator
__device__ float  g_M0[32], g_M1[32], g_M2[32];  // [j*2+o]
__device__ int    g_is64;
__device__ int2   g_edge[MAXE];  // packed (src, dst) int32

// --- init: zero accumulators, fold weights, detect index width ---
__global__ void k_init(const float* __restrict__ W,
                       const float* __restrict__ lam,
                       const unsigned* __restrict__ srcw, int E, int N) {
    int i = blockIdx.x * blockDim.x + threadIdx.x;
    if (i < N) {
        g_deg[i]  = 0;
        g_Vacc[i] = make_float4(0.f, 0.f, 0.f, 0.f);
        g_Tacc[i] = make_float2(0.f, 0.f);
    }
    if (blockIdx.x == 0) {
        if (threadIdx.x < 32) {
            int j = threadIdx.x >> 1, o = threadIdx.x & 1;
            float r = 2.0f / __ldg(lam);
            float A = __ldg(W + o * 48 + j);
            float B = __ldg(W + o * 48 + 16 + j);
            float C = __ldg(W + o * 48 + 32 + j);
            float rm1 = r - 1.0f;
            g_M0[threadIdx.x] = A + rm1 * B + (2.0f * rm1 * rm1 - 1.0f) * C;
            g_M1[threadIdx.x] = -r * B - 4.0f * r * rm1 * C;
            g_M2[threadIdx.x] = 2.0f * r * r * C;
        }
        // int64-vs-int32 detection: high words of valid int64 indices are 0
        __shared__ int s_any;
        if (threadIdx.x == 0) s_any = 0;
        __syncthreads();
        int limit = (E < 4096) ? E : 4096;
        for (int k = threadIdx.x; k < limit; k += blockDim.x)
            if (srcw[2 * k + 1] != 0u) s_any = 1;
        __syncthreads();
        if (threadIdx.x == 0) g_is64 = (s_any == 0) ? 1 : 0;
    }
}

// --- pre-pass: pack edges to int2 + integer degree count (4x batched) ---
__global__ void k_pre(const void* __restrict__ srcv,
                      const void* __restrict__ dstv, int E) {
    int tid = blockIdx.x * blockDim.x + threadIdx.x;
    int S = gridDim.x * blockDim.x;
    int is64 = g_is64;
    int s[UNROLL], d[UNROLL];
    bool v[UNROLL];
#pragma unroll
    for (int j = 0; j < UNROLL; j++) {
        int e = tid + j * S;
        v[j] = (e < E);
        int ee = v[j] ? e : 0;
        if (is64) {
            s[j] = (int)__ldcs((const long long*)srcv + ee);
            d[j] = (int)__ldcs((const long long*)dstv + ee);
        } else {
            s[j] = __ldcs((const int*)srcv + ee);
            d[j] = __ldcs((const int*)dstv + ee);
        }
    }
#pragma unroll
    for (int j = 0; j < UNROLL; j++)
        if (v[j]) __stcs(&g_edge[tid + j * S], make_int2(s[j], d[j]));
#pragma unroll
    for (int j = 0; j < UNROLL; j++)
        if (v[j]) atomicAdd(&g_deg[d[j]], 1);
}

// --- per-node: norm + projections (weights staged in shared) ---
__global__ void k_node(const float* __restrict__ x, int N) {
    __shared__ float sM0[32], sM1[32], sM2[32];
    if (threadIdx.x < 32) {
        sM0[threadIdx.x] = g_M0[threadIdx.x];
        sM1[threadIdx.x] = g_M1[threadIdx.x];
        sM2[threadIdx.x] = g_M2[threadIdx.x];
    }
    __syncthreads();
    int i = blockIdx.x * blockDim.x + threadIdx.x;
    if (i >= N) return;
    float nrm = rsqrtf((float)max(g_deg[i], 1));
    g_norm[i] = nrm;
    float u0 = 0.f, u1 = 0.f, u2 = 0.f, u3 = 0.f, a0 = 0.f, a1 = 0.f;
    const float4* xr = (const float4*)(x + (size_t)i * IN_FEATS);
#pragma unroll
    for (int q = 0; q < 4; q++) {
        float4 xv = __ldg(xr + q);
        float vals[4] = {xv.x, xv.y, xv.z, xv.w};
#pragma unroll
        for (int t = 0; t < 4; t++) {
            int j = q * 4 + t;
            float xj = vals[t];
            a0 += xj * sM0[2 * j];  a1 += xj * sM0[2 * j + 1];
            u0 += xj * sM1[2 * j];  u1 += xj * sM1[2 * j + 1];
            u2 += xj * sM2[2 * j];  u3 += xj * sM2[2 * j + 1];
        }
    }
    g_Us[i] = make_float4(u0 * nrm, u1 * nrm, u2 * nrm, u3 * nrm);
    g_XA[i] = make_float2(a0, a1);
}

// --- propagation pass 1: Vacc[dst] += Us[src]  (4x batched float4 reds) ---
__global__ void k_prop1(int E) {
    int tid = blockIdx.x * blockDim.x + threadIdx.x;
    int S = gridDim.x * blockDim.x;
    int2 ed[UNROLL];
    float4 u[UNROLL];
    bool v[UNROLL];
#pragma unroll
    for (int j = 0; j < UNROLL; j++) {
        int e = tid + j * S;
        v[j] = (e < E);
        ed[j] = __ldcs(&g_edge[v[j] ? e : 0]);
    }
#pragma unroll
    for (int j = 0; j < UNROLL; j++)
        u[j] = __ldg(&g_Us[ed[j].x]);
#pragma unroll
    for (int j = 0; j < UNROLL; j++)
        if (v[j]) atomicAdd(&g_Vacc[ed[j].y], u[j]);
}

// --- finalize pass 1 ---
__global__ void k_fin1(int N) {
    int i = blockIdx.x * blockDim.x + threadIdx.x;
    if (i >= N) return;
    float nrm = g_norm[i];
    float4 v  = g_Vacc[i];
    g_P1[i] = make_float2(v.x * nrm, v.y * nrm);
    float n2 = nrm * nrm;
    g_Zs[i] = make_float2(v.z * n2, v.w * n2);
}

// --- propagation pass 2: Tacc[dst] += Zs[src]  (4x batched float2 reds) ---
__global__ void k_prop2(int E) {
    int tid = blockIdx.x * blockDim.x + threadIdx.x;
    int S = gridDim.x * blockDim.x;
    int2 ed[UNROLL];
    float2 z[UNROLL];
    bool v[UNROLL];
#pragma unroll
    for (int j = 0; j < UNROLL; j++) {
        int e = tid + j * S;
        v[j] = (e < E);
        ed[j] = __ldcs(&g_edge[v[j] ? e : 0]);
    }
#pragma unroll
    for (int j = 0; j < UNROLL; j++)
        z[j] = __ldg(&g_Zs[ed[j].x]);
#pragma unroll
    for (int j = 0; j < UNROLL; j++)
        if (v[j]) atomicAdd(&g_Tacc[ed[j].y], z[j]);
}

// --- epilogue: h = relu(XA + P1 + norm·Tacc) ---
__global__ void k_out(float2* __restrict__ out, int N) {
    int i = blockIdx.x * blockDim.x + threadIdx.x;
    if (i >= N) return;
    float nrm = g_norm[i];
    float2 t = g_Tacc[i], p = g_P1[i], a = g_XA[i];
    out[i] = make_float2(fmaxf(a.x + p.x + t.x * nrm, 0.0f),
                         fmaxf(a.y + p.y + t.y * nrm, 0.0f));
}

extern "C" void kernel_launch(void* const* d_in, const int* in_sizes, int n_in,
                              void* d_out, int out_size) {
    const float* in_feat = (const float*)d_in[0];
    const float* W       = (const float*)d_in[1];
    const void*  src     = d_in[2];
    const void*  dst     = d_in[3];
    const float* lam     = (const float*)d_in[4];

    int N = in_sizes[0] / IN_FEATS;
    int E = in_sizes[2];
    const int TB = 256;
    int nb  = (N + TB - 1) / TB;
    int eb4 = (E + TB * UNROLL - 1) / (TB * UNROLL);

    k_init<<<nb, TB>>>(W, lam, (const unsigned*)src, E, N);
    k_pre<<<eb4, TB>>>(src, dst, E);
    k_node<<<nb, TB>>>(in_feat, N);
    k_prop1<<<eb4, TB>>>(E);
    k_fin1<<<nb, TB>>>(N);
    k_prop2<<<eb4, TB>>>(E);
    k_out<<<nb, TB>>>((float2*)d_out, N);
}